// round 14
// baseline (speedup 1.0000x reference)
#include <cuda_runtime.h>
#include <cuda_bf16.h>

// Problem constants
#define B_   4
#define L_   256
#define DK   48      // D*K
#define D_   8
#define K_   6
#define A_   64
#define O_   64
#define DA   512     // D*A
#define BL   (B_ * L_)

typedef unsigned long long u64;

// Scratch (device globals). Tables hold e-factors: E = ex2(-logit*log2e) so
// exp(-logit_total) = E1[i] * E3[j-i] * C2 (multiplicative split of the sum).
__device__ float g_E1t[DK * BL];    // [dk][b*256+i]   transposed
__device__ float g_C2 [BL * DK];    // [b*256+j][dk]   row-major
__device__ float g_E3t[DK * L_];    // [dk][delta]     transposed
__device__ float g_S  [BL * DA];

#define NEG_LOG2E (-1.4426950408889634f)
#define ECLAMP    1048576.0f

__device__ __forceinline__ float ex2f(float x) {
    float r; asm("ex2.approx.f32 %0, %1;" : "=f"(r) : "f"(x)); return r;
}
__device__ __forceinline__ float rcpf(float x) {
    float r; asm("rcp.approx.f32 %0, %1;" : "=f"(r) : "f"(x)); return r;
}
__device__ __forceinline__ u64 pk2(float lo, float hi) {
    u64 r; asm("mov.b64 %0, {%1, %2};" : "=l"(r) : "f"(lo), "f"(hi)); return r;
}
__device__ __forceinline__ void unpk2(float& lo, float& hi, u64 v) {
    asm("mov.b64 {%0, %1}, %2;" : "=f"(lo), "=f"(hi) : "l"(v));
}
__device__ __forceinline__ u64 mul2(u64 a, u64 b) {
    u64 r; asm("mul.rn.f32x2 %0, %1, %2;" : "=l"(r) : "l"(a), "l"(b)); return r;
}
__device__ __forceinline__ u64 fma2(u64 a, u64 b, u64 c) {
    u64 r; asm("fma.rn.f32x2 %0, %1, %2, %3;" : "=l"(r) : "l"(a), "l"(b), "l"(c)); return r;
}

// ---------------------------------------------------------------------------
// Kernel A: partial e-factors. 144 blocks x 256 threads, 16 rows/block.
//   float4 smem loads in the dot-product loop (stride 68 for 16B alignment).
// ---------------------------------------------------------------------------
__global__ void __launch_bounds__(256)
precompute_kernel(const float* __restrict__ in1,
                  const float* __restrict__ in2,
                  const float* __restrict__ pos,
                  const float* __restrict__ anchors) {
    __shared__ float sa[DK * 68];
    __shared__ float sx[16 * 68];

    const int t  = threadIdx.x;
    const int bi = blockIdx.x;

    int fo, row0, mode;   // mode 0: E1t, 1: C2 row-major, 2: E3t
    const float* src;
    if (bi < 64)       { fo = 0;   row0 = bi * 16;         src = in1; mode = 0; }
    else if (bi < 128) { fo = 64;  row0 = (bi - 64) * 16;  src = in2; mode = 1; }
    else               { fo = 128; row0 = (bi - 128) * 16; src = pos; mode = 2; }

    #pragma unroll
    for (int it = 0; it < 3; it++) {
        const int idx = t + it * 256;
        const int c   = idx >> 4;
        const int f4  = (idx & 15) << 2;
        const float4 v = *(const float4*)(anchors + c * 192 + fo + f4);
        *(float4*)(&sa[c * 68 + f4]) = v;
    }
    {
        const int r   = t >> 4;
        const int f4  = (t & 15) << 2;
        const float4 v = *(const float4*)(src + (row0 + r) * 64 + f4);
        *(float4*)(&sx[r * 68 + f4]) = v;
    }
    __syncthreads();

    const int rg = t & 15;    // row within slab
    const int cg = t >> 4;    // cols cg*3 .. cg*3+2

    float acc0 = 0.f, acc1 = 0.f, acc2 = 0.f;
    const float* a0 = &sa[(cg * 3 + 0) * 68];
    const float* a1 = &sa[(cg * 3 + 1) * 68];
    const float* a2 = &sa[(cg * 3 + 2) * 68];
    const float* x0 = &sx[rg * 68];

    #pragma unroll
    for (int f = 0; f < 64; f += 4) {
        const float4 xv = *(const float4*)(&x0[f]);
        const float4 v0 = *(const float4*)(&a0[f]);
        const float4 v1 = *(const float4*)(&a1[f]);
        const float4 v2 = *(const float4*)(&a2[f]);
        acc0 = fmaf(xv.x, v0.x, acc0); acc0 = fmaf(xv.y, v0.y, acc0);
        acc0 = fmaf(xv.z, v0.z, acc0); acc0 = fmaf(xv.w, v0.w, acc0);
        acc1 = fmaf(xv.x, v1.x, acc1); acc1 = fmaf(xv.y, v1.y, acc1);
        acc1 = fmaf(xv.z, v1.z, acc1); acc1 = fmaf(xv.w, v1.w, acc1);
        acc2 = fmaf(xv.x, v2.x, acc2); acc2 = fmaf(xv.y, v2.y, acc2);
        acc2 = fmaf(xv.z, v2.z, acc2); acc2 = fmaf(xv.w, v2.w, acc2);
    }
    acc0 = ex2f(fminf(acc0 * NEG_LOG2E, 30.f));
    acc1 = ex2f(fminf(acc1 * NEG_LOG2E, 30.f));
    acc2 = ex2f(fminf(acc2 * NEG_LOG2E, 30.f));

    const int row = row0 + rg;
    const int col = cg * 3;
    if (mode == 0) {
        g_E1t[(col + 0) * BL + row] = acc0;
        g_E1t[(col + 1) * BL + row] = acc1;
        g_E1t[(col + 2) * BL + row] = acc2;
    } else if (mode == 1) {
        float* dp = &g_C2[row * DK + col];
        dp[0] = acc0; dp[1] = acc1; dp[2] = acc2;
    } else {
        g_E3t[(col + 0) * L_ + row] = acc0;
        g_E3t[(col + 1) * L_ + row] = acc1;
        g_E3t[(col + 2) * L_ + row] = acc2;
    }
}

// ---------------------------------------------------------------------------
// Kernel B: warp-autonomous pair loop. 2048 blocks x 128 threads, 6 blocks/SM.
//   D-MAJOR task order: d = task>>10, then j descending, warp = b.
//   Co-resident blocks share d -> E1/E3 columns stay L1-resident.
//   Main loop: full 32-i passes, pointer-incremented LDGs; tail keeps mask.
//   Lane-pair split accumulation (acc 16 u64), f32x2 packed outer product.
// ---------------------------------------------------------------------------
__global__ void __launch_bounds__(128, 6)
pair_kernel() {
    __shared__ float red[4][32][33];   // per-warp transpose-reduce scratch

    const int wid  = threadIdx.x >> 5;
    const int lane = threadIdx.x & 31;
    const int par  = lane & 1;

    // d-major: block = (d, j); warps = b
    const int d  = blockIdx.x >> 8;            // 8 d-groups of 256 blocks
    const int j  = (L_ - 1) - (blockIdx.x & 255);   // j descending within d
    const int b  = wid;
    const int dk0 = d * K_;

    const float* c2p = &g_C2[(b * L_ + j) * DK + dk0];
    const float c2_0 = c2p[0], c2_1 = c2p[1], c2_2 = c2p[2];
    const float c2_3 = c2p[3], c2_4 = c2p[4], c2_5 = c2p[5];

    u64 acc[8][2];   // [hi][own-half lo-pair]
    #pragma unroll
    for (int h = 0; h < 8; h++) { acc[h][0] = 0ull; acc[h][1] = 0ull; }

    const float* e1p = &g_E1t[dk0 * BL + b * L_ + lane];   // +32 per pass
    const float* e3p = &g_E3t[dk0 * L_ + j - lane];        // -32 per pass

    const int nfull = j >> 5;
    const int tail  = j & 31;

    for (int p = 0; p < nfull; p++) {
        // e_k = E1*E3*C2 (all lanes valid in full passes)
        const float e0 = fminf(e1p[0 * BL] * (e3p[0 * L_] * c2_0), ECLAMP);
        const float e1 = fminf(e1p[1 * BL] * (e3p[1 * L_] * c2_1), ECLAMP);
        const float e2 = fminf(e1p[2 * BL] * (e3p[2 * L_] * c2_2), ECLAMP);
        const float e3 = fminf(e1p[3 * BL] * (e3p[3 * L_] * c2_3), ECLAMP);
        const float e4 = fminf(e1p[4 * BL] * (e3p[4 * L_] * c2_4), ECLAMP);
        const float e5 = fminf(e1p[5 * BL] * (e3p[5 * L_] * c2_5), ECLAMP);
        e1p += 32; e3p -= 32;

        const float Z  = ((1.f + e0) * (1.f + e1)) * ((1.f + e2) * (1.f + e3))
                       * ((1.f + e4) * (1.f + e5));
        const float rm = rcpf(Z);   // no mask in full passes

        // lo halves: A = {e0e1e2, e1e2 | e0e2, e2}, B = {e0e1, e1 | e0, 1}
        const float c01 = e0 * e1;
        const u64 P01 = pk2(c01, e1);
        const u64 P23 = pk2(e0, 1.f);
        const u64 E2b = pk2(e2, e2);
        const u64 LA0 = mul2(P01, E2b);
        const u64 LA1 = mul2(P23, E2b);

        // exchange lo half with partner
        const u64 s0 = par ? LA0 : P01;
        const u64 s1 = par ? LA1 : P23;
        const u64 rLO0 = __shfl_xor_sync(0xffffffffu, s0, 1);
        const u64 rLO1 = __shfl_xor_sync(0xffffffffu, s1, 1);
        const u64 kLO0 = par ? P01 : LA0;
        const u64 kLO1 = par ? P23 : LA1;

        // hi for own i, partner's hi by direct shfl
        const float c34 = e3 * e4, e5rm = e5 * rm;
        float hiO[8];
        hiO[0] = c34 * e5rm; hiO[1] = e4 * e5rm; hiO[2] = e3 * e5rm; hiO[3] = e5rm;
        hiO[4] = c34 * rm;   hiO[5] = e4 * rm;   hiO[6] = e3 * rm;   hiO[7] = rm;
        float hiP[8];
        #pragma unroll
        for (int h = 0; h < 8; h++)
            hiP[h] = __shfl_xor_sync(0xffffffffu, hiO[h], 1);

        #pragma unroll
        for (int h = 0; h < 8; h++) {
            const u64 hbO = pk2(hiO[h], hiO[h]);
            acc[h][0] = fma2(hbO, kLO0, acc[h][0]);
            acc[h][1] = fma2(hbO, kLO1, acc[h][1]);
        }
        #pragma unroll
        for (int h = 0; h < 8; h++) {
            const u64 hbP = pk2(hiP[h], hiP[h]);
            acc[h][0] = fma2(hbP, rLO0, acc[h][0]);
            acc[h][1] = fma2(hbP, rLO1, acc[h][1]);
        }
    }

    if (tail) {
        const int i  = nfull * 32 + lane;     // i <= 255 always
        const int o3 = max(j - i, 0);
        const float* e3t = &g_E3t[dk0 * L_ + o3];

        const float e0 = fminf(e1p[0 * BL] * (e3t[0 * L_] * c2_0), ECLAMP);
        const float e1 = fminf(e1p[1 * BL] * (e3t[1 * L_] * c2_1), ECLAMP);
        const float e2 = fminf(e1p[2 * BL] * (e3t[2 * L_] * c2_2), ECLAMP);
        const float e3 = fminf(e1p[3 * BL] * (e3t[3 * L_] * c2_3), ECLAMP);
        const float e4 = fminf(e1p[4 * BL] * (e3t[4 * L_] * c2_4), ECLAMP);
        const float e5 = fminf(e1p[5 * BL] * (e3t[5 * L_] * c2_5), ECLAMP);

        const float Z  = ((1.f + e0) * (1.f + e1)) * ((1.f + e2) * (1.f + e3))
                       * ((1.f + e4) * (1.f + e5));
        const float m  = (i < j) ? 1.0f : 0.0f;
        const float rm = rcpf(Z) * m;

        const float c01 = e0 * e1;
        const u64 P01 = pk2(c01, e1);
        const u64 P23 = pk2(e0, 1.f);
        const u64 E2b = pk2(e2, e2);
        const u64 LA0 = mul2(P01, E2b);
        const u64 LA1 = mul2(P23, E2b);

        const u64 s0 = par ? LA0 : P01;
        const u64 s1 = par ? LA1 : P23;
        const u64 rLO0 = __shfl_xor_sync(0xffffffffu, s0, 1);
        const u64 rLO1 = __shfl_xor_sync(0xffffffffu, s1, 1);
        const u64 kLO0 = par ? P01 : LA0;
        const u64 kLO1 = par ? P23 : LA1;

        const float c34 = e3 * e4, e5rm = e5 * rm;
        float hiO[8];
        hiO[0] = c34 * e5rm; hiO[1] = e4 * e5rm; hiO[2] = e3 * e5rm; hiO[3] = e5rm;
        hiO[4] = c34 * rm;   hiO[5] = e4 * rm;   hiO[6] = e3 * rm;   hiO[7] = rm;
        float hiP[8];
        #pragma unroll
        for (int h = 0; h < 8; h++)
            hiP[h] = __shfl_xor_sync(0xffffffffu, hiO[h], 1);

        #pragma unroll
        for (int h = 0; h < 8; h++) {
            const u64 hbO = pk2(hiO[h], hiO[h]);
            acc[h][0] = fma2(hbO, kLO0, acc[h][0]);
            acc[h][1] = fma2(hbO, kLO1, acc[h][1]);
        }
        #pragma unroll
        for (int h = 0; h < 8; h++) {
            const u64 hbP = pk2(hiP[h], hiP[h]);
            acc[h][0] = fma2(hbP, rLO0, acc[h][0]);
            acc[h][1] = fma2(hbP, rLO1, acc[h][1]);
        }
    }

    // unpack: av[h][t], t=0..3 -> address a = h*8 + par*4 + t
    float av[8][4];
    #pragma unroll
    for (int h = 0; h < 8; h++) {
        unpk2(av[h][0], av[h][1], acc[h][0]);
        unpk2(av[h][2], av[h][3], acc[h][1]);
    }

    // single-round transpose-reduce: red[lane][h*4+t]
    float (*rw)[33] = red[wid];
    #pragma unroll
    for (int h = 0; h < 8; h++) {
        #pragma unroll
        for (int t2 = 0; t2 < 4; t2++) rw[lane][h * 4 + t2] = av[h][t2];
    }
    __syncwarp();

    float* sbase = &g_S[((size_t)(b * L_ + j)) * DA + d * A_];
    #pragma unroll
    for (int half = 0; half < 2; half++) {
        const int o  = lane + half * 32;       // output address 0..63
        const int hh = o >> 3;
        const int l  = o & 7;
        const int pr = (l >> 2) & 1;           // parity of source lanes
        const int c  = hh * 4 + (l & 3);
        float sum = 0.f;
        #pragma unroll
        for (int k = 0; k < 16; k++) sum += rw[2 * k + pr][c];
        sbase[o] = sum;
    }
}

// ---------------------------------------------------------------------------
// Kernel C: out[row, o] = sum_da S[row, da] * W[da, o].
// 128 blocks (8 rows each) x 256 threads, split-k=2, 2x2 register tiles.
// ---------------------------------------------------------------------------
__global__ void __launch_bounds__(256)
final_gemm(const float* __restrict__ W, float* __restrict__ out) {
    __shared__ float sW[128 * 64];
    __shared__ float sS[8][132];
    __shared__ float red[128][4];

    const int t    = threadIdx.x;
    const int row0 = blockIdx.x * 8;
    const int kh   = t >> 7;
    const int u    = t & 127;
    const int tr   = u >> 5;
    const int tc   = u & 31;

    float a00 = 0.f, a01 = 0.f, a10 = 0.f, a11 = 0.f;

    for (int chnk = 0; chnk < 4; chnk++) {
        const int k0 = chnk * 128;
        const float4* Wv = (const float4*)(W + k0 * 64);
        #pragma unroll
        for (int it = 0; it < 8; it++)
            ((float4*)sW)[t + it * 256] = Wv[t + it * 256];
        {
            const int r  = t >> 5;
            const int c4 = (t & 31) << 2;
            const float4 v = *(const float4*)(&g_S[(row0 + r) * DA + k0 + c4]);
            float* dp = &sS[r][c4];
            dp[0] = v.x; dp[1] = v.y; dp[2] = v.z; dp[3] = v.w;
        }
        __syncthreads();

        const int kb = kh * 64;
        #pragma unroll 8
        for (int kk = 0; kk < 64; kk++) {
            const int k = kb + kk;
            const float2 w = *(const float2*)(&sW[k * 64 + tc * 2]);
            const float s0 = sS[tr * 2][k];
            const float s1 = sS[tr * 2 + 1][k];
            a00 = fmaf(s0, w.x, a00);
            a01 = fmaf(s0, w.y, a01);
            a10 = fmaf(s1, w.x, a10);
            a11 = fmaf(s1, w.y, a11);
        }
        __syncthreads();
    }

    if (kh == 1) {
        red[u][0] = a00; red[u][1] = a01; red[u][2] = a10; red[u][3] = a11;
    }
    __syncthreads();
    if (kh == 0) {
        a00 += red[u][0]; a01 += red[u][1]; a10 += red[u][2]; a11 += red[u][3];
        const int r = row0 + tr * 2, c = tc * 2;
        out[r * O_ + c]           = a00;
        out[r * O_ + c + 1]       = a01;
        out[(r + 1) * O_ + c]     = a10;
        out[(r + 1) * O_ + c + 1] = a11;
    }
}

// ---------------------------------------------------------------------------
extern "C" void kernel_launch(void* const* d_in, const int* in_sizes, int n_in,
                              void* d_out, int out_size) {
    const float* in1     = (const float*)d_in[0];
    const float* in2     = (const float*)d_in[1];
    const float* pos     = (const float*)d_in[2];
    const float* anchors = (const float*)d_in[3];
    const float* lut     = (const float*)d_in[4];
    float* out = (float*)d_out;

    precompute_kernel<<<144, 256>>>(in1, in2, pos, anchors);
    pair_kernel<<<2048, 128>>>();
    final_gemm<<<(B_ * L_) / 8, 256>>>(lut, out);
}

// round 16
// speedup vs baseline: 1.0589x; 1.0589x over previous
#include <cuda_runtime.h>
#include <cuda_bf16.h>

// Problem constants
#define B_   4
#define L_   256
#define DK   48      // D*K
#define D_   8
#define K_   6
#define A_   64
#define O_   64
#define DA   512     // D*A
#define BL   (B_ * L_)

typedef unsigned long long u64;

// Scratch. k-interleaved e-factor tables: pair (2q, 2q+1) of dk packed in one
// float2. 48 dk -> 24 k2 rows. (R14 bug: these were sized 3 rows -> OOB.)
__device__ float2 g_E1p[24 * BL];   // [k2][b*256+i] -> (E_{2k2}, E_{2k2+1})
__device__ float  g_C2 [BL * DK];   // [b*256+j][dk]
__device__ float2 g_E3p[24 * L_];   // [k2][delta]
__device__ float  g_S  [BL * DA];

#define NEG_LOG2E (-1.4426950408889634f)
#define ECLAMP    1048576.0f

__device__ __forceinline__ float ex2f(float x) {
    float r; asm("ex2.approx.f32 %0, %1;" : "=f"(r) : "f"(x)); return r;
}
__device__ __forceinline__ float rcpf(float x) {
    float r; asm("rcp.approx.f32 %0, %1;" : "=f"(r) : "f"(x)); return r;
}
__device__ __forceinline__ u64 pk2(float lo, float hi) {
    u64 r; asm("mov.b64 %0, {%1, %2};" : "=l"(r) : "f"(lo), "f"(hi)); return r;
}
__device__ __forceinline__ void unpk2(float& lo, float& hi, u64 v) {
    asm("mov.b64 {%0, %1}, %2;" : "=f"(lo), "=f"(hi) : "l"(v));
}
__device__ __forceinline__ u64 mul2(u64 a, u64 b) {
    u64 r; asm("mul.rn.f32x2 %0, %1, %2;" : "=l"(r) : "l"(a), "l"(b)); return r;
}
__device__ __forceinline__ u64 fma2(u64 a, u64 b, u64 c) {
    u64 r; asm("fma.rn.f32x2 %0, %1, %2, %3;" : "=l"(r) : "l"(a), "l"(b), "l"(c)); return r;
}

// ---------------------------------------------------------------------------
// Kernel A: partial e-factors. 144 blocks x 256 threads, 16 rows/block.
// ---------------------------------------------------------------------------
__global__ void __launch_bounds__(256)
precompute_kernel(const float* __restrict__ in1,
                  const float* __restrict__ in2,
                  const float* __restrict__ pos,
                  const float* __restrict__ anchors) {
    __shared__ float sa[DK * 68];
    __shared__ float sx[16 * 68];

    const int t  = threadIdx.x;
    const int bi = blockIdx.x;

    int fo, row0, mode;   // mode 0: E1p, 1: C2 row-major, 2: E3p
    const float* src;
    if (bi < 64)       { fo = 0;   row0 = bi * 16;         src = in1; mode = 0; }
    else if (bi < 128) { fo = 64;  row0 = (bi - 64) * 16;  src = in2; mode = 1; }
    else               { fo = 128; row0 = (bi - 128) * 16; src = pos; mode = 2; }

    #pragma unroll
    for (int it = 0; it < 3; it++) {
        const int idx = t + it * 256;
        const int c   = idx >> 4;
        const int f4  = (idx & 15) << 2;
        const float4 v = *(const float4*)(anchors + c * 192 + fo + f4);
        *(float4*)(&sa[c * 68 + f4]) = v;
    }
    {
        const int r   = t >> 4;
        const int f4  = (t & 15) << 2;
        const float4 v = *(const float4*)(src + (row0 + r) * 64 + f4);
        *(float4*)(&sx[r * 68 + f4]) = v;
    }
    __syncthreads();

    const int rg = t & 15;    // row within slab
    const int cg = t >> 4;    // cols cg*3 .. cg*3+2

    float acc0 = 0.f, acc1 = 0.f, acc2 = 0.f;
    const float* a0 = &sa[(cg * 3 + 0) * 68];
    const float* a1 = &sa[(cg * 3 + 1) * 68];
    const float* a2 = &sa[(cg * 3 + 2) * 68];
    const float* x0 = &sx[rg * 68];

    #pragma unroll
    for (int f = 0; f < 64; f += 4) {
        const float4 xv = *(const float4*)(&x0[f]);
        const float4 v0 = *(const float4*)(&a0[f]);
        const float4 v1 = *(const float4*)(&a1[f]);
        const float4 v2 = *(const float4*)(&a2[f]);
        acc0 = fmaf(xv.x, v0.x, acc0); acc0 = fmaf(xv.y, v0.y, acc0);
        acc0 = fmaf(xv.z, v0.z, acc0); acc0 = fmaf(xv.w, v0.w, acc0);
        acc1 = fmaf(xv.x, v1.x, acc1); acc1 = fmaf(xv.y, v1.y, acc1);
        acc1 = fmaf(xv.z, v1.z, acc1); acc1 = fmaf(xv.w, v1.w, acc1);
        acc2 = fmaf(xv.x, v2.x, acc2); acc2 = fmaf(xv.y, v2.y, acc2);
        acc2 = fmaf(xv.z, v2.z, acc2); acc2 = fmaf(xv.w, v2.w, acc2);
    }
    acc0 = ex2f(fminf(acc0 * NEG_LOG2E, 30.f));
    acc1 = ex2f(fminf(acc1 * NEG_LOG2E, 30.f));
    acc2 = ex2f(fminf(acc2 * NEG_LOG2E, 30.f));

    const int row = row0 + rg;
    const int col = cg * 3;
    float res[3] = {acc0, acc1, acc2};
    if (mode == 0) {
        #pragma unroll
        for (int q = 0; q < 3; q++) {
            const int c = col + q;
            float* dst = (float*)&g_E1p[(c >> 1) * BL + row];
            dst[c & 1] = res[q];
        }
    } else if (mode == 1) {
        float* dp = &g_C2[row * DK + col];
        dp[0] = res[0]; dp[1] = res[1]; dp[2] = res[2];
    } else {
        #pragma unroll
        for (int q = 0; q < 3; q++) {
            const int c = col + q;
            float* dst = (float*)&g_E3p[(c >> 1) * L_ + row];
            dst[c & 1] = res[q];
        }
    }
}

// ---------------------------------------------------------------------------
// Kernel B: warp-autonomous pair loop. 2048 blocks x 128 threads, 6 blocks/SM.
//   j-major task order (task = blockIdx*4 + wid). Per pass: 6 LDG.64 (packed
//   k-pairs), product-Z soft LUT, lane-pair split accumulation, inline
//   partner shfl. Tail pass keeps clamps + mask.
// ---------------------------------------------------------------------------
__global__ void __launch_bounds__(128, 6)
pair_kernel() {
    __shared__ float red[4][32][33];   // per-warp transpose-reduce scratch

    const int wid  = threadIdx.x >> 5;
    const int lane = threadIdx.x & 31;
    const int par  = lane & 1;
    const int task = blockIdx.x * 4 + wid;

    const int j   = (L_ - 1) - (task >> 5);   // big-j tasks first
    const int sub = task & 31;
    const int b   = sub & 3;
    const int d   = sub >> 2;
    const int dk0 = d * K_;

    const float* c2p = &g_C2[(b * L_ + j) * DK + dk0];
    const float c2_0 = c2p[0], c2_1 = c2p[1], c2_2 = c2p[2];
    const float c2_3 = c2p[3], c2_4 = c2p[4], c2_5 = c2p[5];

    u64 acc[8][2];   // [hi][own-half lo-pair]
    #pragma unroll
    for (int h = 0; h < 8; h++) { acc[h][0] = 0ull; acc[h][1] = 0ull; }

    // packed table pointers: k2 = dk0/2 .. dk0/2+2
    const float2* e1p2 = &g_E1p[(dk0 >> 1) * BL + b * L_ + lane];  // +32/pass
    const float2* e3p2 = &g_E3p[(dk0 >> 1) * L_ + j - lane];       // -32/pass

    const int nfull = j >> 5;
    const int tail  = j & 31;

    for (int p = 0; p < nfull; p++) {
        const float2 a01 = e1p2[0 * BL];
        const float2 a23 = e1p2[1 * BL];
        const float2 a45 = e1p2[2 * BL];
        const float2 b01 = e3p2[0 * L_];
        const float2 b23 = e3p2[1 * L_];
        const float2 b45 = e3p2[2 * L_];
        e1p2 += 32; e3p2 -= 32;

        const float e0 = fminf(a01.x * (b01.x * c2_0), ECLAMP);
        const float e1 = fminf(a01.y * (b01.y * c2_1), ECLAMP);
        const float e2 = fminf(a23.x * (b23.x * c2_2), ECLAMP);
        const float e3 = fminf(a23.y * (b23.y * c2_3), ECLAMP);
        const float e4 = fminf(a45.x * (b45.x * c2_4), ECLAMP);
        const float e5 = fminf(a45.y * (b45.y * c2_5), ECLAMP);

        const float Z  = ((1.f + e0) * (1.f + e1)) * ((1.f + e2) * (1.f + e3))
                       * ((1.f + e4) * (1.f + e5));
        const float rm = rcpf(Z);

        // lo halves: A = {e0e1e2, e1e2 | e0e2, e2}, B = {e0e1, e1 | e0, 1}
        const float c01 = e0 * e1;
        const u64 P01 = pk2(c01, e1);
        const u64 P23 = pk2(e0, 1.f);
        const u64 E2b = pk2(e2, e2);
        const u64 LA0 = mul2(P01, E2b);
        const u64 LA1 = mul2(P23, E2b);

        const u64 s0 = par ? LA0 : P01;
        const u64 s1 = par ? LA1 : P23;
        const u64 rLO0 = __shfl_xor_sync(0xffffffffu, s0, 1);
        const u64 rLO1 = __shfl_xor_sync(0xffffffffu, s1, 1);
        const u64 kLO0 = par ? P01 : LA0;
        const u64 kLO1 = par ? P23 : LA1;

        const float c34 = e3 * e4, e5rm = e5 * rm;
        float hiO[8];
        hiO[0] = c34 * e5rm; hiO[1] = e4 * e5rm; hiO[2] = e3 * e5rm; hiO[3] = e5rm;
        hiO[4] = c34 * rm;   hiO[5] = e4 * rm;   hiO[6] = e3 * rm;   hiO[7] = rm;

        #pragma unroll
        for (int h = 0; h < 8; h++) {
            const u64 hbO = pk2(hiO[h], hiO[h]);
            acc[h][0] = fma2(hbO, kLO0, acc[h][0]);
            acc[h][1] = fma2(hbO, kLO1, acc[h][1]);
        }
        #pragma unroll
        for (int h = 0; h < 8; h++) {
            const float hp = __shfl_xor_sync(0xffffffffu, hiO[h], 1);
            const u64 hbP = pk2(hp, hp);
            acc[h][0] = fma2(hbP, rLO0, acc[h][0]);
            acc[h][1] = fma2(hbP, rLO1, acc[h][1]);
        }
    }

    if (tail) {
        const int i  = nfull * 32 + lane;     // i <= 255 always
        const int o3 = max(j - i, 0);
        const float2* e3t = &g_E3p[(dk0 >> 1) * L_ + o3];

        const float2 a01 = e1p2[0 * BL];
        const float2 a23 = e1p2[1 * BL];
        const float2 a45 = e1p2[2 * BL];
        const float2 b01 = e3t[0 * L_];
        const float2 b23 = e3t[1 * L_];
        const float2 b45 = e3t[2 * L_];

        const float e0 = fminf(a01.x * (b01.x * c2_0), ECLAMP);
        const float e1 = fminf(a01.y * (b01.y * c2_1), ECLAMP);
        const float e2 = fminf(a23.x * (b23.x * c2_2), ECLAMP);
        const float e3 = fminf(a23.y * (b23.y * c2_3), ECLAMP);
        const float e4 = fminf(a45.x * (b45.x * c2_4), ECLAMP);
        const float e5 = fminf(a45.y * (b45.y * c2_5), ECLAMP);

        const float Z  = ((1.f + e0) * (1.f + e1)) * ((1.f + e2) * (1.f + e3))
                       * ((1.f + e4) * (1.f + e5));
        const float m  = (i < j) ? 1.0f : 0.0f;
        const float rm = rcpf(Z) * m;

        const float c01 = e0 * e1;
        const u64 P01 = pk2(c01, e1);
        const u64 P23 = pk2(e0, 1.f);
        const u64 E2b = pk2(e2, e2);
        const u64 LA0 = mul2(P01, E2b);
        const u64 LA1 = mul2(P23, E2b);

        const u64 s0 = par ? LA0 : P01;
        const u64 s1 = par ? LA1 : P23;
        const u64 rLO0 = __shfl_xor_sync(0xffffffffu, s0, 1);
        const u64 rLO1 = __shfl_xor_sync(0xffffffffu, s1, 1);
        const u64 kLO0 = par ? P01 : LA0;
        const u64 kLO1 = par ? P23 : LA1;

        const float c34 = e3 * e4, e5rm = e5 * rm;
        float hiO[8];
        hiO[0] = c34 * e5rm; hiO[1] = e4 * e5rm; hiO[2] = e3 * e5rm; hiO[3] = e5rm;
        hiO[4] = c34 * rm;   hiO[5] = e4 * rm;   hiO[6] = e3 * rm;   hiO[7] = rm;

        #pragma unroll
        for (int h = 0; h < 8; h++) {
            const u64 hbO = pk2(hiO[h], hiO[h]);
            acc[h][0] = fma2(hbO, kLO0, acc[h][0]);
            acc[h][1] = fma2(hbO, kLO1, acc[h][1]);
        }
        #pragma unroll
        for (int h = 0; h < 8; h++) {
            const float hp = __shfl_xor_sync(0xffffffffu, hiO[h], 1);
            const u64 hbP = pk2(hp, hp);
            acc[h][0] = fma2(hbP, rLO0, acc[h][0]);
            acc[h][1] = fma2(hbP, rLO1, acc[h][1]);
        }
    }

    // unpack: av[h][t], t=0..3 -> address a = h*8 + par*4 + t
    float av[8][4];
    #pragma unroll
    for (int h = 0; h < 8; h++) {
        unpk2(av[h][0], av[h][1], acc[h][0]);
        unpk2(av[h][2], av[h][3], acc[h][1]);
    }

    // single-round transpose-reduce: red[lane][h*4+t]
    float (*rw)[33] = red[wid];
    #pragma unroll
    for (int h = 0; h < 8; h++) {
        #pragma unroll
        for (int t2 = 0; t2 < 4; t2++) rw[lane][h * 4 + t2] = av[h][t2];
    }
    __syncwarp();

    float* sbase = &g_S[((size_t)(b * L_ + j)) * DA + d * A_];
    #pragma unroll
    for (int half = 0; half < 2; half++) {
        const int o  = lane + half * 32;       // output address 0..63
        const int hh = o >> 3;
        const int l  = o & 7;
        const int pr = (l >> 2) & 1;           // parity of source lanes
        const int c  = hh * 4 + (l & 3);
        float sum = 0.f;
        #pragma unroll
        for (int k = 0; k < 16; k++) sum += rw[2 * k + pr][c];
        sbase[o] = sum;
    }
}

// ---------------------------------------------------------------------------
// Kernel C: out[row, o] = sum_da S[row, da] * W[da, o].
// 128 blocks (8 rows each) x 256 threads, split-k=2, 2x2 register tiles.
// ---------------------------------------------------------------------------
__global__ void __launch_bounds__(256)
final_gemm(const float* __restrict__ W, float* __restrict__ out) {
    __shared__ float sW[128 * 64];
    __shared__ float sS[8][132];
    __shared__ float red[128][4];

    const int t    = threadIdx.x;
    const int row0 = blockIdx.x * 8;
    const int kh   = t >> 7;
    const int u    = t & 127;
    const int tr   = u >> 5;
    const int tc   = u & 31;

    float a00 = 0.f, a01 = 0.f, a10 = 0.f, a11 = 0.f;

    for (int chnk = 0; chnk < 4; chnk++) {
        const int k0 = chnk * 128;
        const float4* Wv = (const float4*)(W + k0 * 64);
        #pragma unroll
        for (int it = 0; it < 8; it++)
            ((float4*)sW)[t + it * 256] = Wv[t + it * 256];
        {
            const int r  = t >> 5;
            const int c4 = (t & 31) << 2;
            const float4 v = *(const float4*)(&g_S[(row0 + r) * DA + k0 + c4]);
            float* dp = &sS[r][c4];
            dp[0] = v.x; dp[1] = v.y; dp[2] = v.z; dp[3] = v.w;
        }
        __syncthreads();

        const int kb = kh * 64;
        #pragma unroll 8
        for (int kk = 0; kk < 64; kk++) {
            const int k = kb + kk;
            const float2 w = *(const float2*)(&sW[k * 64 + tc * 2]);
            const float s0 = sS[tr * 2][k];
            const float s1 = sS[tr * 2 + 1][k];
            a00 = fmaf(s0, w.x, a00);
            a01 = fmaf(s0, w.y, a01);
            a10 = fmaf(s1, w.x, a10);
            a11 = fmaf(s1, w.y, a11);
        }
        __syncthreads();
    }

    if (kh == 1) {
        red[u][0] = a00; red[u][1] = a01; red[u][2] = a10; red[u][3] = a11;
    }
    __syncthreads();
    if (kh == 0) {
        a00 += red[u][0]; a01 += red[u][1]; a10 += red[u][2]; a11 += red[u][3];
        const int r = row0 + tr * 2, c = tc * 2;
        out[r * O_ + c]           = a00;
        out[r * O_ + c + 1]       = a01;
        out[(r + 1) * O_ + c]     = a10;
        out[(r + 1) * O_ + c + 1] = a11;
    }
}

// ---------------------------------------------------------------------------
extern "C" void kernel_launch(void* const* d_in, const int* in_sizes, int n_in,
                              void* d_out, int out_size) {
    const float* in1     = (const float*)d_in[0];
    const float* in2     = (const float*)d_in[1];
    const float* pos     = (const float*)d_in[2];
    const float* anchors = (const float*)d_in[3];
    const float* lut     = (const float*)d_in[4];
    float* out = (float*)d_out;

    precompute_kernel<<<144, 256>>>(in1, in2, pos, anchors);
    pair_kernel<<<2048, 128>>>();
    final_gemm<<<(B_ * L_) / 8, 256>>>(lut, out);
}